// round 1
// baseline (speedup 1.0000x reference)
#include <cuda_runtime.h>

#define Bz 8
#define Cz 2048
#define Hz 4
#define Dz 32
#define HD 128   // Hz*Dz
#define QT 64
#define KT 64

// Scratch (allocation-free rule: device globals)
__device__ float g_Q[Bz*Hz*Cz*Dz];
__device__ float g_K[Bz*Hz*Cz*Dz];
__device__ float g_V[Bz*Hz*Cz*Dz];
__device__ float g_att[Bz*Cz*HD];

// ---------------------------------------------------------------------------
// Kernel 1: fused QKV projection.  grid (B*C/32, 3), block 128.
// Computes 32 rows x 128 cols of (x @ W); writes to g_Q/g_K/g_V in
// [b][h][c][d] layout. Q pre-scaled by 1/sqrt(D).
// ---------------------------------------------------------------------------
__global__ __launch_bounds__(128) void qkv_proj(
    const float* __restrict__ x,
    const float* __restrict__ Wq,
    const float* __restrict__ Wk,
    const float* __restrict__ Wv)
{
    __shared__ float xs[32*128];
    const int rt = blockIdx.x;
    const int m  = blockIdx.y;                 // 0=Q 1=K 2=V
    const float* __restrict__ W = (m == 0) ? Wq : ((m == 1) ? Wk : Wv);
    float* __restrict__ out = (m == 0) ? g_Q : ((m == 1) ? g_K : g_V);
    const int tid = threadIdx.x;

    // stage 32x128 x-tile (contiguous 16KB)
    const float4* xg = (const float4*)(x + (size_t)rt * 32 * 128);
    float4* xs4w = (float4*)xs;
    #pragma unroll
    for (int i = 0; i < 8; i++) xs4w[tid + i*128] = xg[tid + i*128];
    __syncthreads();

    const int col = tid;
    float acc[32];
    #pragma unroll
    for (int r = 0; r < 32; r++) acc[r] = 0.f;

    const float4* xs4 = (const float4*)xs;
    #pragma unroll 4
    for (int d4 = 0; d4 < 32; d4++) {
        const float w0 = W[(d4*4+0)*128 + col];
        const float w1 = W[(d4*4+1)*128 + col];
        const float w2 = W[(d4*4+2)*128 + col];
        const float w3 = W[(d4*4+3)*128 + col];
        #pragma unroll
        for (int r = 0; r < 32; r++) {
            const float4 xv = xs4[r*32 + d4];   // broadcast, conflict-free
            acc[r] += xv.x*w0 + xv.y*w1 + xv.z*w2 + xv.w*w3;
        }
    }

    const float scale = (m == 0) ? 0.17677669529663687f : 1.0f;  // 1/sqrt(32)
    const int h = col >> 5, dd = col & 31;
    const int row0 = rt * 32;
    #pragma unroll
    for (int r = 0; r < 32; r++) {
        const int row = row0 + r;
        const int b = row >> 11, c = row & 2047;
        out[(((size_t)(b*Hz + h))*Cz + c)*Dz + dd] = acc[r] * scale;
    }
}

// ---------------------------------------------------------------------------
// Kernel 2: attention.  grid (C/QT, B), block 256 (= 4 heads x 64 q-rows).
// One thread per (h, q-row); Q row + 32-wide output accumulator in registers.
// Streams K/V/adj tiles through smem. Scores are bounded (|s| <~ 2), so
// softmax uses plain exp without max-subtraction (mathematically identical).
// ---------------------------------------------------------------------------
__global__ __launch_bounds__(256, 2) void attn_kernel(const float* __restrict__ adj)
{
    extern __shared__ float sm[];
    float* Ks   = sm;                       // [4][64][32]
    float* Vs   = sm + Hz*KT*Dz;            // [4][64][32]
    float* adjs = sm + 2*Hz*KT*Dz;          // [64][65] (pad -> conflict-free)

    const int tid = threadIdx.x;
    const int h   = tid >> 6;
    const int qi  = tid & 63;
    const int q0  = blockIdx.x * QT;
    const int b   = blockIdx.y;

    // own Q row -> registers
    float4 q4[8];
    const float4* Qp = (const float4*)(g_Q + (((size_t)(b*Hz + h))*Cz + q0 + qi)*Dz);
    #pragma unroll
    for (int i = 0; i < 8; i++) q4[i] = Qp[i];

    float acc[32];
    #pragma unroll
    for (int i = 0; i < 32; i++) acc[i] = 0.f;
    float l = 0.f;

    const float4* Kg = (const float4*)(g_K + ((size_t)b*Hz)*Cz*Dz);
    const float4* Vg = (const float4*)(g_V + ((size_t)b*Hz)*Cz*Dz);
    const float* adj_base = adj + ((size_t)b*Cz + q0)*Cz;

    #pragma unroll 1
    for (int k0 = 0; k0 < Cz; k0 += KT) {
        __syncthreads();  // guard smem reuse
        // stage K,V tiles: 2048 float4 each; 8 per thread, coalesced
        {
            float4* Ks4 = (float4*)Ks;
            float4* Vs4 = (float4*)Vs;
            #pragma unroll
            for (int i = 0; i < 8; i++) {
                const int idx  = tid + i*256;        // 0..2047
                const int hh   = idx >> 9;
                const int rem  = idx & 511;
                const int krow = rem >> 3;
                const int d4   = rem & 7;
                const int g    = (hh*Cz + k0 + krow)*8 + d4;
                Ks4[idx] = Kg[g];
                Vs4[idx] = Vg[g];
            }
            // adj tile: 64x64 floats; scalar stores into padded rows
            #pragma unroll
            for (int i = 0; i < 16; i++) {
                const int idx = tid + i*256;
                const int r   = idx >> 6;
                const int cc  = idx & 63;
                adjs[r*65 + cc] = adj_base[(size_t)r*Cz + k0 + cc];
            }
        }
        __syncthreads();

        const float* Kh   = Ks + h*KT*Dz;
        const float* Vh   = Vs + h*KT*Dz;
        const float* arow = adjs + qi*65;

        #pragma unroll 2
        for (int kk = 0; kk < KT; kk += 4) {
            float s0 = 0.f, s1 = 0.f, s2 = 0.f, s3 = 0.f;
            #pragma unroll
            for (int d = 0; d < 8; d++) {
                const float4 qq = q4[d];
                const float4 k0v = *(const float4*)(Kh + (kk+0)*32 + d*4);
                const float4 k1v = *(const float4*)(Kh + (kk+1)*32 + d*4);
                const float4 k2v = *(const float4*)(Kh + (kk+2)*32 + d*4);
                const float4 k3v = *(const float4*)(Kh + (kk+3)*32 + d*4);
                s0 += qq.x*k0v.x + qq.y*k0v.y + qq.z*k0v.z + qq.w*k0v.w;
                s1 += qq.x*k1v.x + qq.y*k1v.y + qq.z*k1v.z + qq.w*k1v.w;
                s2 += qq.x*k2v.x + qq.y*k2v.y + qq.z*k2v.z + qq.w*k2v.w;
                s3 += qq.x*k3v.x + qq.y*k3v.y + qq.z*k3v.z + qq.w*k3v.w;
            }
            // adjacency gate + LeakyReLU(0.2) (= fmaxf(x, 0.2x)) + exp
            float t0 = s0 * arow[kk+0]; t0 = fmaxf(t0, 0.2f*t0);
            float t1 = s1 * arow[kk+1]; t1 = fmaxf(t1, 0.2f*t1);
            float t2 = s2 * arow[kk+2]; t2 = fmaxf(t2, 0.2f*t2);
            float t3 = s3 * arow[kk+3]; t3 = fmaxf(t3, 0.2f*t3);
            const float p0 = __expf(t0);
            const float p1 = __expf(t1);
            const float p2 = __expf(t2);
            const float p3 = __expf(t3);
            l += (p0 + p1) + (p2 + p3);
            #pragma unroll
            for (int d = 0; d < 8; d++) {
                const float4 v0 = *(const float4*)(Vh + (kk+0)*32 + d*4);
                const float4 v1 = *(const float4*)(Vh + (kk+1)*32 + d*4);
                const float4 v2 = *(const float4*)(Vh + (kk+2)*32 + d*4);
                const float4 v3 = *(const float4*)(Vh + (kk+3)*32 + d*4);
                acc[d*4+0] += p0*v0.x + p1*v1.x + p2*v2.x + p3*v3.x;
                acc[d*4+1] += p0*v0.y + p1*v1.y + p2*v2.y + p3*v3.y;
                acc[d*4+2] += p0*v0.z + p1*v1.z + p2*v2.z + p3*v3.z;
                acc[d*4+3] += p0*v0.w + p1*v1.w + p2*v2.w + p3*v3.w;
            }
        }
    }

    const float rl = 1.0f / l;
    float* op = g_att + (((size_t)b*Cz + q0 + qi)*Hz + h)*Dz;   // (B,C,H*D) concat layout
    #pragma unroll
    for (int d = 0; d < 32; d++) op[d] = acc[d] * rl;
}

// ---------------------------------------------------------------------------
// Kernel 3: output projection  out = g_att @ Wo + bo.  grid 512, block 128.
// ---------------------------------------------------------------------------
__global__ __launch_bounds__(128) void out_proj(
    const float* __restrict__ Wo,
    const float* __restrict__ bo,
    float* __restrict__ out)
{
    __shared__ float xs[32*128];
    const int rt  = blockIdx.x;
    const int tid = threadIdx.x;

    const float4* xg = (const float4*)(g_att + (size_t)rt * 32 * 128);
    float4* xs4w = (float4*)xs;
    #pragma unroll
    for (int i = 0; i < 8; i++) xs4w[tid + i*128] = xg[tid + i*128];
    __syncthreads();

    const int col = tid;
    float acc[32];
    #pragma unroll
    for (int r = 0; r < 32; r++) acc[r] = 0.f;

    const float4* xs4 = (const float4*)xs;
    #pragma unroll 4
    for (int d4 = 0; d4 < 32; d4++) {
        const float w0 = Wo[(d4*4+0)*128 + col];
        const float w1 = Wo[(d4*4+1)*128 + col];
        const float w2 = Wo[(d4*4+2)*128 + col];
        const float w3 = Wo[(d4*4+3)*128 + col];
        #pragma unroll
        for (int r = 0; r < 32; r++) {
            const float4 xv = xs4[r*32 + d4];
            acc[r] += xv.x*w0 + xv.y*w1 + xv.z*w2 + xv.w*w3;
        }
    }

    const float bias = bo[col];
    const int row0 = rt * 32;
    #pragma unroll
    for (int r = 0; r < 32; r++)
        out[(size_t)(row0 + r)*128 + col] = acc[r] + bias;
}

// ---------------------------------------------------------------------------
extern "C" void kernel_launch(void* const* d_in, const int* in_sizes, int n_in,
                              void* d_out, int out_size)
{
    const float* x   = (const float*)d_in[0];
    const float* adj = (const float*)d_in[1];
    const float* Wq  = (const float*)d_in[2];
    const float* Wk  = (const float*)d_in[3];
    const float* Wv  = (const float*)d_in[4];
    const float* Wo  = (const float*)d_in[5];
    const float* bo  = (const float*)d_in[6];
    float* out = (float*)d_out;

    const int smem = (2*Hz*KT*Dz + QT*65) * (int)sizeof(float);  // 82176 B
    cudaFuncSetAttribute(attn_kernel, cudaFuncAttributeMaxDynamicSharedMemorySize, smem);

    qkv_proj<<<dim3(Bz*Cz/32, 3), 128>>>(x, Wq, Wk, Wv);
    attn_kernel<<<dim3(Cz/QT, Bz), 256, smem>>>(adj);
    out_proj<<<Bz*Cz/32, 128>>>(Wo, bo, out);
}

// round 2
// speedup vs baseline: 1.0742x; 1.0742x over previous
#include <cuda_runtime.h>

#define Bz 8
#define Cz 2048
#define Hz 4
#define Dz 32
#define HD 128   // Hz*Dz
#define QT 64
#define KT 64

typedef unsigned long long u64;

// Scratch (allocation-free rule: device globals)
__device__ float g_Q[Bz*Hz*Cz*Dz];
__device__ float g_K[Bz*Hz*Cz*Dz];
__device__ float g_V[Bz*Hz*Cz*Dz];
__device__ float g_att[Bz*Cz*HD];

// ---- packed f32x2 helpers (FFMA2 path; ptxas never emits these from C++) ----
__device__ __forceinline__ u64 ffma2(u64 a, u64 b, u64 c) {
    u64 d;
    asm("fma.rn.f32x2 %0, %1, %2, %3;" : "=l"(d) : "l"(a), "l"(b), "l"(c));
    return d;
}
__device__ __forceinline__ u64 fadd2(u64 a, u64 b) {
    u64 d;
    asm("add.rn.f32x2 %0, %1, %2;" : "=l"(d) : "l"(a), "l"(b));
    return d;
}
__device__ __forceinline__ u64 fmul2(u64 a, u64 b) {
    u64 d;
    asm("mul.rn.f32x2 %0, %1, %2;" : "=l"(d) : "l"(a), "l"(b));
    return d;
}
__device__ __forceinline__ u64 pack2(float lo, float hi) {
    u64 d;
    asm("mov.b64 %0, {%1, %2};" : "=l"(d) : "f"(lo), "f"(hi));
    return d;
}
__device__ __forceinline__ float2 unpack2(u64 v) {
    float lo, hi;
    asm("mov.b64 {%0, %1}, %2;" : "=f"(lo), "=f"(hi) : "l"(v));
    return make_float2(lo, hi);
}

// ---------------------------------------------------------------------------
// Kernel 1: fused QKV projection.  grid (B*C/32, 3), block 128.
// f32x2-packed along k. Q pre-scaled by 1/sqrt(D).
// ---------------------------------------------------------------------------
__global__ __launch_bounds__(128) void qkv_proj(
    const float* __restrict__ x,
    const float* __restrict__ Wq,
    const float* __restrict__ Wk,
    const float* __restrict__ Wv)
{
    __shared__ float xs[32*128];
    const int rt = blockIdx.x;
    const int m  = blockIdx.y;                 // 0=Q 1=K 2=V
    const float* __restrict__ W = (m == 0) ? Wq : ((m == 1) ? Wk : Wv);
    float* __restrict__ out = (m == 0) ? g_Q : ((m == 1) ? g_K : g_V);
    const int tid = threadIdx.x;

    const float4* xg = (const float4*)(x + (size_t)rt * 32 * 128);
    float4* xs4w = (float4*)xs;
    #pragma unroll
    for (int i = 0; i < 8; i++) xs4w[tid + i*128] = xg[tid + i*128];
    __syncthreads();

    const int col = tid;
    u64 acc2[32];
    #pragma unroll
    for (int r = 0; r < 32; r++) acc2[r] = 0ull;

    const ulonglong2* xs2 = (const ulonglong2*)xs;
    #pragma unroll 4
    for (int d4 = 0; d4 < 32; d4++) {
        const u64 w01 = pack2(W[(d4*4+0)*128 + col], W[(d4*4+1)*128 + col]);
        const u64 w23 = pack2(W[(d4*4+2)*128 + col], W[(d4*4+3)*128 + col]);
        #pragma unroll
        for (int r = 0; r < 32; r++) {
            const ulonglong2 xv = xs2[r*32 + d4];   // broadcast LDS.128
            acc2[r] = ffma2(xv.x, w01, acc2[r]);
            acc2[r] = ffma2(xv.y, w23, acc2[r]);
        }
    }

    const float scale = (m == 0) ? 0.17677669529663687f : 1.0f;  // 1/sqrt(32)
    const int h = col >> 5, dd = col & 31;
    const int row0 = rt * 32;
    #pragma unroll
    for (int r = 0; r < 32; r++) {
        const int row = row0 + r;
        const int b = row >> 11, c = row & 2047;
        const float2 u = unpack2(acc2[r]);
        out[(((size_t)(b*Hz + h))*Cz + c)*Dz + dd] = (u.x + u.y) * scale;
    }
}

// ---------------------------------------------------------------------------
// Kernel 2: attention.  grid (C/QT, B), block 128 (= 4 heads x 32 threads),
// occupancy 2. Each thread handles TWO q-rows (qi, qi+32) so each broadcast
// K/V shared-load feeds 4 packed FMAs. All dot products via fma.rn.f32x2.
// Scores are bounded (|s| <~ 2) => plain exp softmax, no max subtraction.
// ---------------------------------------------------------------------------
__global__ __launch_bounds__(128, 2) void attn_kernel(const float* __restrict__ adj)
{
    extern __shared__ float sm[];
    float* Ks   = sm;                       // [4][64][32]
    float* Vs   = sm + Hz*KT*Dz;            // [4][64][32]
    float* adjs = sm + 2*Hz*KT*Dz;          // [64][65] (pad -> conflict-free)

    const int tid = threadIdx.x;
    const int h   = tid >> 5;               // warp == head
    const int qi  = tid & 31;
    const int q0  = blockIdx.x * QT;
    const int b   = blockIdx.y;

    // two Q rows -> packed registers
    u64 qa[16], qb[16];
    {
        const ulonglong2* QpA = (const ulonglong2*)(g_Q + (((size_t)(b*Hz + h))*Cz + q0 + qi)*Dz);
        const ulonglong2* QpB = (const ulonglong2*)(g_Q + (((size_t)(b*Hz + h))*Cz + q0 + qi + 32)*Dz);
        #pragma unroll
        for (int i = 0; i < 8; i++) {
            ulonglong2 ta = QpA[i]; qa[2*i] = ta.x; qa[2*i+1] = ta.y;
            ulonglong2 tb = QpB[i]; qb[2*i] = tb.x; qb[2*i+1] = tb.y;
        }
    }

    u64 accA[16], accB[16];
    #pragma unroll
    for (int i = 0; i < 16; i++) { accA[i] = 0ull; accB[i] = 0ull; }
    float lA = 0.f, lB = 0.f;

    const float4* Kg = (const float4*)(g_K + ((size_t)b*Hz)*Cz*Dz);
    const float4* Vg = (const float4*)(g_V + ((size_t)b*Hz)*Cz*Dz);
    const float* adj_base = adj + ((size_t)b*Cz + q0)*Cz;

    #pragma unroll 1
    for (int k0 = 0; k0 < Cz; k0 += KT) {
        __syncthreads();  // guard smem reuse
        {
            float4* Ks4 = (float4*)Ks;
            float4* Vs4 = (float4*)Vs;
            #pragma unroll
            for (int i = 0; i < 16; i++) {
                const int idx  = tid + i*128;        // 0..2047
                const int hh   = idx >> 9;
                const int rem  = idx & 511;
                const int krow = rem >> 3;
                const int d4   = rem & 7;
                const int g    = (hh*Cz + k0 + krow)*8 + d4;
                Ks4[idx] = Kg[g];
                Vs4[idx] = Vg[g];
            }
            #pragma unroll
            for (int i = 0; i < 32; i++) {
                const int idx = tid + i*128;
                const int r   = idx >> 6;
                const int cc  = idx & 63;
                adjs[r*65 + cc] = adj_base[(size_t)r*Cz + k0 + cc];
            }
        }
        __syncthreads();

        const float* Kh  = Ks + h*KT*Dz;
        const float* Vh  = Vs + h*KT*Dz;
        const float* arA = adjs + qi*65;
        const float* arB = adjs + (qi + 32)*65;

        #pragma unroll 1
        for (int kk = 0; kk < KT; kk++) {
            // ---- scores for both q-rows against key kk (broadcast LDS) ----
            const ulonglong2* k2p = (const ulonglong2*)(Kh + kk*32);
            u64 a0 = 0ull, a1 = 0ull, b0 = 0ull, b1 = 0ull;
            #pragma unroll
            for (int i = 0; i < 8; i++) {
                const ulonglong2 kv = k2p[i];
                a0 = ffma2(qa[2*i],   kv.x, a0);
                a1 = ffma2(qa[2*i+1], kv.y, a1);
                b0 = ffma2(qb[2*i],   kv.x, b0);
                b1 = ffma2(qb[2*i+1], kv.y, b1);
            }
            const float2 sa = unpack2(fadd2(a0, a1));
            const float2 sb = unpack2(fadd2(b0, b1));
            const float sA = sa.x + sa.y;
            const float sB = sb.x + sb.y;

            // adjacency gate + LeakyReLU(0.2) + exp
            float tA = sA * arA[kk]; tA = fmaxf(tA, 0.2f*tA);
            float tB = sB * arB[kk]; tB = fmaxf(tB, 0.2f*tB);
            const float pA = __expf(tA);
            const float pB = __expf(tB);
            lA += pA;
            lB += pB;

            // ---- accumulate P*V for both rows ----
            const u64 pA2 = pack2(pA, pA);
            const u64 pB2 = pack2(pB, pB);
            const ulonglong2* v2p = (const ulonglong2*)(Vh + kk*32);
            #pragma unroll
            for (int i = 0; i < 8; i++) {
                const ulonglong2 vv = v2p[i];
                accA[2*i]   = ffma2(pA2, vv.x, accA[2*i]);
                accA[2*i+1] = ffma2(pA2, vv.y, accA[2*i+1]);
                accB[2*i]   = ffma2(pB2, vv.x, accB[2*i]);
                accB[2*i+1] = ffma2(pB2, vv.y, accB[2*i+1]);
            }
        }
    }

    // epilogue: normalize and store (B,C,H*D) concat layout
    {
        const u64 rA2 = pack2(1.0f/lA, 1.0f/lA);
        const u64 rB2 = pack2(1.0f/lB, 1.0f/lB);
        float* opA = g_att + (((size_t)b*Cz + q0 + qi)*Hz + h)*Dz;
        float* opB = g_att + (((size_t)b*Cz + q0 + qi + 32)*Hz + h)*Dz;
        #pragma unroll
        for (int i = 0; i < 16; i++) {
            const float2 ua = unpack2(fmul2(accA[i], rA2));
            const float2 ub = unpack2(fmul2(accB[i], rB2));
            *(float2*)(opA + 2*i) = ua;
            *(float2*)(opB + 2*i) = ub;
        }
    }
}

// ---------------------------------------------------------------------------
// Kernel 3: output projection  out = g_att @ Wo + bo.  grid 512, block 128.
// ---------------------------------------------------------------------------
__global__ __launch_bounds__(128) void out_proj(
    const float* __restrict__ Wo,
    const float* __restrict__ bo,
    float* __restrict__ out)
{
    __shared__ float xs[32*128];
    const int rt  = blockIdx.x;
    const int tid = threadIdx.x;

    const float4* xg = (const float4*)(g_att + (size_t)rt * 32 * 128);
    float4* xs4w = (float4*)xs;
    #pragma unroll
    for (int i = 0; i < 8; i++) xs4w[tid + i*128] = xg[tid + i*128];
    __syncthreads();

    const int col = tid;
    u64 acc2[32];
    #pragma unroll
    for (int r = 0; r < 32; r++) acc2[r] = 0ull;

    const ulonglong2* xs2 = (const ulonglong2*)xs;
    #pragma unroll 4
    for (int d4 = 0; d4 < 32; d4++) {
        const u64 w01 = pack2(Wo[(d4*4+0)*128 + col], Wo[(d4*4+1)*128 + col]);
        const u64 w23 = pack2(Wo[(d4*4+2)*128 + col], Wo[(d4*4+3)*128 + col]);
        #pragma unroll
        for (int r = 0; r < 32; r++) {
            const ulonglong2 xv = xs2[r*32 + d4];
            acc2[r] = ffma2(xv.x, w01, acc2[r]);
            acc2[r] = ffma2(xv.y, w23, acc2[r]);
        }
    }

    const float bias = bo[col];
    const int row0 = rt * 32;
    #pragma unroll
    for (int r = 0; r < 32; r++) {
        const float2 u = unpack2(acc2[r]);
        out[(size_t)(row0 + r)*128 + col] = u.x + u.y + bias;
    }
}

// ---------------------------------------------------------------------------
extern "C" void kernel_launch(void* const* d_in, const int* in_sizes, int n_in,
                              void* d_out, int out_size)
{
    const float* x   = (const float*)d_in[0];
    const float* adj = (const float*)d_in[1];
    const float* Wq  = (const float*)d_in[2];
    const float* Wk  = (const float*)d_in[3];
    const float* Wv  = (const float*)d_in[4];
    const float* Wo  = (const float*)d_in[5];
    const float* bo  = (const float*)d_in[6];
    float* out = (float*)d_out;

    const int smem = (2*Hz*KT*Dz + QT*65) * (int)sizeof(float);  // 82176 B
    cudaFuncSetAttribute(attn_kernel, cudaFuncAttributeMaxDynamicSharedMemorySize, smem);

    qkv_proj<<<dim3(Bz*Cz/32, 3), 128>>>(x, Wq, Wk, Wv);
    attn_kernel<<<dim3(Cz/QT, Bz), 128, smem>>>(adj);
    out_proj<<<Bz*Cz/32, 128>>>(Wo, bo, out);
}

// round 6
// speedup vs baseline: 2.4145x; 2.2477x over previous
#include <cuda_runtime.h>
#include <cuda_bf16.h>

typedef unsigned int u32;
typedef unsigned long long u64;

#define Bz 8
#define Cz 2048
#define HD 128
#define QT 64
#define KT 64
#define NIT (Cz/KT)

// Scratch (allocation-free rule). Row layout [b*C + c][h*32 + d]
__device__ float g_Q[Bz*Cz*HD];
__device__ float g_K[Bz*Cz*HD];
__device__ float g_V[Bz*Cz*HD];
__device__ float g_att[Bz*Cz*HD];

// ---- smem byte offsets (attention kernel) ----
// K/V tiles: [4 h][64 key][40 bf16 pad] = 20480 B each
#define K_HI 0
#define K_LO 20480
#define V_HI 40960
#define V_LO 61440
#define ADJ  81920              // [64][68] fp32 = 17408
#define SMEMT 99328

// ---------------- helpers ---------------------------------------------------
__device__ __forceinline__ u32 smem_u32(const void* p) {
    u32 a;
    asm("{ .reg .u64 t; cvta.to.shared.u64 t, %1; cvt.u32.u64 %0, t; }" : "=r"(a) : "l"(p));
    return a;
}
__device__ __forceinline__ u32 cvt2(float hi, float lo) {   // pack: hi->upper, lo->lower
    u32 r; asm("cvt.rn.bf16x2.f32 %0, %1, %2;" : "=r"(r) : "f"(hi), "f"(lo)); return r;
}
__device__ __forceinline__ float2 ub2(u32 v) {
    __nv_bfloat162 t = *reinterpret_cast<__nv_bfloat162*>(&v);
    return __bfloat1622float2(t);
}
__device__ __forceinline__ void split4(float4 v, uint2& hi, uint2& lo) {
    u32 h0 = cvt2(v.y, v.x), h1 = cvt2(v.w, v.z);
    float2 f0 = ub2(h0), f1 = ub2(h1);
    lo = make_uint2(cvt2(v.y - f0.y, v.x - f0.x), cvt2(v.w - f1.y, v.z - f1.x));
    hi = make_uint2(h0, h1);
}
__device__ __forceinline__ void ldsm4(u32* r, u32 addr) {
    asm volatile("ldmatrix.sync.aligned.m8n8.x4.shared.b16 {%0,%1,%2,%3}, [%4];"
        : "=r"(r[0]), "=r"(r[1]), "=r"(r[2]), "=r"(r[3]) : "r"(addr));
}
__device__ __forceinline__ void ldsm4t(u32* r, u32 addr) {
    asm volatile("ldmatrix.sync.aligned.m8n8.x4.trans.shared.b16 {%0,%1,%2,%3}, [%4];"
        : "=r"(r[0]), "=r"(r[1]), "=r"(r[2]), "=r"(r[3]) : "r"(addr));
}
__device__ __forceinline__ void mma16816(float* c, const u32* a, const u32* b) {
    asm volatile("mma.sync.aligned.m16n8k16.row.col.f32.bf16.bf16.f32 "
        "{%0,%1,%2,%3}, {%4,%5,%6,%7}, {%8,%9}, {%0,%1,%2,%3};"
        : "+f"(c[0]), "+f"(c[1]), "+f"(c[2]), "+f"(c[3])
        : "r"(a[0]), "r"(a[1]), "r"(a[2]), "r"(a[3]), "r"(b[0]), "r"(b[1]));
}
// ---- packed f32x2 (projection kernels) ----
__device__ __forceinline__ u64 ffma2(u64 a, u64 b, u64 c) {
    u64 d; asm("fma.rn.f32x2 %0, %1, %2, %3;" : "=l"(d) : "l"(a), "l"(b), "l"(c)); return d;
}
__device__ __forceinline__ u64 pack2(float lo, float hi) {
    u64 d; asm("mov.b64 %0, {%1, %2};" : "=l"(d) : "f"(lo), "f"(hi)); return d;
}
__device__ __forceinline__ float2 unpack2(u64 v) {
    float lo, hi; asm("mov.b64 {%0, %1}, %2;" : "=f"(lo), "=f"(hi) : "l"(v)); return make_float2(lo, hi);
}

// ---------------------------------------------------------------------------
// Kernel 1: fused QKV projection (FFMA2). Q pre-scaled by 1/sqrt(32).
// ---------------------------------------------------------------------------
__global__ __launch_bounds__(128) void qkv_proj(
    const float* __restrict__ x, const float* __restrict__ Wq,
    const float* __restrict__ Wk, const float* __restrict__ Wv)
{
    __shared__ float xs[32*128];
    const int rt = blockIdx.x, m = blockIdx.y, tid = threadIdx.x;
    const float* __restrict__ W = (m == 0) ? Wq : ((m == 1) ? Wk : Wv);
    float* __restrict__ out = (m == 0) ? g_Q : ((m == 1) ? g_K : g_V);

    const float4* xg = (const float4*)(x + (size_t)rt * 32 * 128);
    float4* xs4w = (float4*)xs;
    #pragma unroll
    for (int i = 0; i < 8; i++) xs4w[tid + i*128] = xg[tid + i*128];
    __syncthreads();

    const int col = tid;
    u64 acc2[32];
    #pragma unroll
    for (int r = 0; r < 32; r++) acc2[r] = 0ull;
    const ulonglong2* xs2 = (const ulonglong2*)xs;
    #pragma unroll 4
    for (int d4 = 0; d4 < 32; d4++) {
        const u64 w01 = pack2(W[(d4*4+0)*128 + col], W[(d4*4+1)*128 + col]);
        const u64 w23 = pack2(W[(d4*4+2)*128 + col], W[(d4*4+3)*128 + col]);
        #pragma unroll
        for (int r = 0; r < 32; r++) {
            const ulonglong2 xv = xs2[r*32 + d4];
            acc2[r] = ffma2(xv.x, w01, acc2[r]);
            acc2[r] = ffma2(xv.y, w23, acc2[r]);
        }
    }
    const float scale = (m == 0) ? 0.17677669529663687f : 1.0f;
    const int row0 = rt * 32;
    #pragma unroll
    for (int r = 0; r < 32; r++) {
        const float2 u = unpack2(acc2[r]);
        out[(size_t)(row0 + r)*128 + col] = (u.x + u.y) * scale;
    }
}

// ---------------------------------------------------------------------------
// Kernel 2: mma.sync bf16 hi/lo attention. grid (C/64, B), 256 threads.
// warp = (h = wid&3, qsub = wid>>2); each warp: 32 q-rows x 1 head.
// ---------------------------------------------------------------------------
__global__ __launch_bounds__(256, 2) void attn_mma(const float* __restrict__ adj)
{
    extern __shared__ char sm[];
    const u32 smb = smem_u32(sm);
    const int tid = threadIdx.x;
    const int wid = tid >> 5, lane = tid & 31;
    const int h = wid & 3, qsub = wid >> 2;
    const int r = lane >> 2, qq = lane & 3;
    const int q0 = blockIdx.x * QT, b = blockIdx.y;

    // ---- Q A-fragments (hi/lo) for m16 tiles m=0,1; k16 slices j=0,1 ----
    u32 qhi[2][2][4], qlo[2][2][4];
    {
        const float* Qb = g_Q + ((size_t)(b*Cz) + q0 + qsub*32)*HD + h*32;
        #pragma unroll
        for (int m = 0; m < 2; m++)
            #pragma unroll
            for (int j = 0; j < 2; j++)
                #pragma unroll
                for (int p = 0; p < 4; p++) {
                    const int row = 16*m + r + (p & 1)*8;
                    const int col = 16*j + 2*qq + (p >> 1)*8;
                    const float2 v = *(const float2*)(Qb + (size_t)row*HD + col);
                    const u32 h2 = cvt2(v.y, v.x);
                    const float2 hf = ub2(h2);
                    qhi[m][j][p] = h2;
                    qlo[m][j][p] = cvt2(v.y - hf.y, v.x - hf.x);
                }
    }

    float out[2][4][4];
    #pragma unroll
    for (int m = 0; m < 2; m++)
        #pragma unroll
        for (int dt = 0; dt < 4; dt++)
            #pragma unroll
            for (int k = 0; k < 4; k++) out[m][dt][k] = 0.f;
    float rs[4] = {0.f, 0.f, 0.f, 0.f};

    // per-lane ldmatrix address components
    const u32 kofs = (u32)((lane & 7)*80 + (lane >> 3)*16);
    const u32 vofs = (u32)((lane & 15)*80 + (lane >> 4)*16);
    const u32 KhiB = smb + K_HI + h*5120 + kofs;
    const u32 KloB = smb + K_LO + h*5120 + kofs;
    const u32 VhiB = smb + V_HI + h*5120 + vofs;
    const u32 VloB = smb + V_LO + h*5120 + vofs;
    const float* adjs = (const float*)(sm + ADJ) + (qsub*32 + r)*68 + 2*qq;
    const float* adj_g = adj + ((size_t)b*Cz + q0)*Cz;

    #pragma unroll 1
    for (int it = 0; it < NIT; it++) {
        const int k0 = it * KT;
        __syncthreads();
        // ---- stage K, V (hi/lo bf16) and adj ----
        {
            const float4* Kg = (const float4*)(g_K + ((size_t)b*Cz + k0)*HD);
            const float4* Vg = (const float4*)(g_V + ((size_t)b*Cz + k0)*HD);
            #pragma unroll
            for (int i = 0; i < 8; i++) {
                const int e = tid + i*256;
                const int hh = e >> 9, rem = e & 511, key = rem >> 3, dg = rem & 7;
                const int gofs = key*32 + hh*8 + dg;
                const u32 so = (u32)(hh*5120 + key*80 + dg*8);
                uint2 hi, lo;
                split4(Kg[gofs], hi, lo);
                *(uint2*)(sm + K_HI + so) = hi;
                *(uint2*)(sm + K_LO + so) = lo;
                split4(Vg[gofs], hi, lo);
                *(uint2*)(sm + V_HI + so) = hi;
                *(uint2*)(sm + V_LO + so) = lo;
            }
            #pragma unroll
            for (int i = 0; i < 4; i++) {
                const int e = tid + i*256;
                const int row = e >> 4, c4 = e & 15;
                const float4 a = *(const float4*)(adj_g + (size_t)row*Cz + k0 + c4*4);
                *(float4*)(sm + ADJ + (row*68 + c4*4)*4) = a;
            }
        }
        __syncthreads();

        // ---- compute: 4 k16 slices of 16 keys each ----
        #pragma unroll
        for (int j = 0; j < 4; j++) {
            u32 pa[2][4], pl[2][4];
            #pragma unroll
            for (int ii = 0; ii < 2; ii++) {
                const int i = 2*j + ii;
                u32 bh[4], bl[4];
                ldsm4(bh, KhiB + i*640);
                ldsm4(bl, KloB + i*640);
                #pragma unroll
                for (int m = 0; m < 2; m++) {
                    float S[4] = {0.f, 0.f, 0.f, 0.f};
                    mma16816(S, qhi[m][0], bh + 0);
                    mma16816(S, qhi[m][1], bh + 2);
                    mma16816(S, qhi[m][0], bl + 0);
                    mma16816(S, qhi[m][1], bl + 2);
                    mma16816(S, qlo[m][0], bh + 0);
                    mma16816(S, qlo[m][1], bh + 2);

                    const float* ar = adjs + (16*m)*68 + 8*i;
                    const float2 a01 = *(const float2*)ar;
                    const float2 a23 = *(const float2*)(ar + 8*68);
                    float t0 = S[0]*a01.x; t0 = fmaxf(t0, 0.2f*t0);
                    float t1 = S[1]*a01.y; t1 = fmaxf(t1, 0.2f*t1);
                    float t2 = S[2]*a23.x; t2 = fmaxf(t2, 0.2f*t2);
                    float t3 = S[3]*a23.y; t3 = fmaxf(t3, 0.2f*t3);
                    const float p0 = __expf(t0), p1 = __expf(t1);
                    const float p2 = __expf(t2), p3 = __expf(t3);
                    rs[2*m]   += p0 + p1;
                    rs[2*m+1] += p2 + p3;
                    const u32 h01 = cvt2(p1, p0); const float2 f01 = ub2(h01);
                    const u32 h23 = cvt2(p3, p2); const float2 f23 = ub2(h23);
                    pa[m][2*ii]   = h01;
                    pa[m][2*ii+1] = h23;
                    pl[m][2*ii]   = cvt2(p1 - f01.y, p0 - f01.x);
                    pl[m][2*ii+1] = cvt2(p3 - f23.y, p2 - f23.x);
                }
            }
            // ---- PV for slice j: V^T B-frags via ldmatrix.trans ----
            u32 vh[8], vl[8];
            ldsm4t(vh,     VhiB + j*1280);
            ldsm4t(vh + 4, VhiB + j*1280 + 32);
            ldsm4t(vl,     VloB + j*1280);
            ldsm4t(vl + 4, VloB + j*1280 + 32);
            #pragma unroll
            for (int m = 0; m < 2; m++)
                #pragma unroll
                for (int dt = 0; dt < 4; dt++) {
                    mma16816(out[m][dt], pa[m], vh + dt*2);
                    mma16816(out[m][dt], pa[m], vl + dt*2);
                    mma16816(out[m][dt], pl[m], vh + dt*2);
                }
        }
    }

    // ---- rowsum reduce across quad, normalize, store ----
    #pragma unroll
    for (int k = 0; k < 4; k++) {
        rs[k] += __shfl_xor_sync(0xFFFFFFFFu, rs[k], 1);
        rs[k] += __shfl_xor_sync(0xFFFFFFFFu, rs[k], 2);
    }
    const float inv[4] = {1.f/rs[0], 1.f/rs[1], 1.f/rs[2], 1.f/rs[3]};

    float* Ob = g_att + ((size_t)(b*Cz) + q0 + qsub*32)*HD + h*32;
    #pragma unroll
    for (int m = 0; m < 2; m++)
        #pragma unroll
        for (int dt = 0; dt < 4; dt++) {
            float2 v0 = make_float2(out[m][dt][0]*inv[2*m],   out[m][dt][1]*inv[2*m]);
            float2 v1 = make_float2(out[m][dt][2]*inv[2*m+1], out[m][dt][3]*inv[2*m+1]);
            *(float2*)(Ob + (size_t)(16*m + r)*HD     + 8*dt + 2*qq) = v0;
            *(float2*)(Ob + (size_t)(16*m + r + 8)*HD + 8*dt + 2*qq) = v1;
        }
}

// ---------------------------------------------------------------------------
// Kernel 3: output projection (FFMA2).
// ---------------------------------------------------------------------------
__global__ __launch_bounds__(128) void out_proj(
    const float* __restrict__ Wo, const float* __restrict__ bo,
    float* __restrict__ out)
{
    __shared__ float xs[32*128];
    const int rt = blockIdx.x, tid = threadIdx.x;

    const float4* xg = (const float4*)(g_att + (size_t)rt * 32 * 128);
    float4* xs4w = (float4*)xs;
    #pragma unroll
    for (int i = 0; i < 8; i++) xs4w[tid + i*128] = xg[tid + i*128];
    __syncthreads();

    const int col = tid;
    u64 acc2[32];
    #pragma unroll
    for (int r = 0; r < 32; r++) acc2[r] = 0ull;
    const ulonglong2* xs2 = (const ulonglong2*)xs;
    #pragma unroll 4
    for (int d4 = 0; d4 < 32; d4++) {
        const u64 w01 = pack2(Wo[(d4*4+0)*128 + col], Wo[(d4*4+1)*128 + col]);
        const u64 w23 = pack2(Wo[(d4*4+2)*128 + col], Wo[(d4*4+3)*128 + col]);
        #pragma unroll
        for (int r = 0; r < 32; r++) {
            const ulonglong2 xv = xs2[r*32 + d4];
            acc2[r] = ffma2(xv.x, w01, acc2[r]);
            acc2[r] = ffma2(xv.y, w23, acc2[r]);
        }
    }
    const float bias = bo[col];
    const int row0 = rt * 32;
    #pragma unroll
    for (int r = 0; r < 32; r++) {
        const float2 u = unpack2(acc2[r]);
        out[(size_t)(row0 + r)*128 + col] = u.x + u.y + bias;
    }
}

// ---------------------------------------------------------------------------
extern "C" void kernel_launch(void* const* d_in, const int* in_sizes, int n_in,
                              void* d_out, int out_size)
{
    const float* x   = (const float*)d_in[0];
    const float* adj = (const float*)d_in[1];
    const float* Wq  = (const float*)d_in[2];
    const float* Wk  = (const float*)d_in[3];
    const float* Wv  = (const float*)d_in[4];
    const float* Wo  = (const float*)d_in[5];
    const float* bo  = (const float*)d_in[6];
    float* out = (float*)d_out;

    cudaFuncSetAttribute(attn_mma, cudaFuncAttributeMaxDynamicSharedMemorySize, SMEMT);

    qkv_proj<<<dim3(Bz*Cz/32, 3), 128>>>(x, Wq, Wk, Wv);
    attn_mma<<<dim3(Cz/QT, Bz), 256, SMEMT>>>(adj);
    out_proj<<<Bz*Cz/32, 128>>>(Wo, bo, out);
}

// round 7
// speedup vs baseline: 2.8494x; 1.1801x over previous
#include <cuda_runtime.h>
#include <cuda_bf16.h>

typedef unsigned int u32;
typedef unsigned long long u64;

#define Bz 8
#define Cz 2048
#define HD 128
#define QT 128
#define KT 64
#define NIT (Cz/KT)
#define LOG2E 1.4426950408889634f

// hi/lo bf16 scratch, packed as u32 bf16x2 (even col in low half)
__device__ u32 g_Qhi[Bz*Cz*64], g_Qlo[Bz*Cz*64];        // [b*C + c][64]
__device__ u32 g_Khi[Bz*4*Cz*16], g_Klo[Bz*4*Cz*16];    // [b*4+h][key][16]
__device__ u32 g_Vhi[Bz*4*Cz*16], g_Vlo[Bz*4*Cz*16];
__device__ u32 g_Ahi[Bz*Cz*64], g_Alo[Bz*Cz*64];        // attention output

// ---------------- helpers ---------------------------------------------------
__device__ __forceinline__ u32 smem_u32(const void* p) {
    u32 a;
    asm("{ .reg .u64 t; cvta.to.shared.u64 t, %1; cvt.u32.u64 %0, t; }" : "=r"(a) : "l"(p));
    return a;
}
__device__ __forceinline__ u32 cvt2(float hi, float lo) {
    u32 r; asm("cvt.rn.bf16x2.f32 %0, %1, %2;" : "=r"(r) : "f"(hi), "f"(lo)); return r;
}
__device__ __forceinline__ float2 ub2(u32 v) {
    __nv_bfloat162 t = *reinterpret_cast<__nv_bfloat162*>(&v);
    return __bfloat1622float2(t);
}
// split pair (x0 -> low, x1 -> high) into hi/lo bf16x2 words
__device__ __forceinline__ void split2(float x0, float x1, u32& hi, u32& lo) {
    hi = cvt2(x1, x0);
    float2 f = ub2(hi);
    lo = cvt2(x1 - f.y, x0 - f.x);
}
__device__ __forceinline__ float ex2f(float x) {
    float y; asm("ex2.approx.f32 %0, %1;" : "=f"(y) : "f"(x)); return y;
}
__device__ __forceinline__ void ldsm4(u32* r, u32 addr) {
    asm volatile("ldmatrix.sync.aligned.m8n8.x4.shared.b16 {%0,%1,%2,%3}, [%4];"
        : "=r"(r[0]), "=r"(r[1]), "=r"(r[2]), "=r"(r[3]) : "r"(addr));
}
__device__ __forceinline__ void ldsm4t(u32* r, u32 addr) {
    asm volatile("ldmatrix.sync.aligned.m8n8.x4.trans.shared.b16 {%0,%1,%2,%3}, [%4];"
        : "=r"(r[0]), "=r"(r[1]), "=r"(r[2]), "=r"(r[3]) : "r"(addr));
}
__device__ __forceinline__ void mma16816(float* c, const u32* a, const u32* b) {
    asm volatile("mma.sync.aligned.m16n8k16.row.col.f32.bf16.bf16.f32 "
        "{%0,%1,%2,%3}, {%4,%5,%6,%7}, {%8,%9}, {%0,%1,%2,%3};"
        : "+f"(c[0]), "+f"(c[1]), "+f"(c[2]), "+f"(c[3])
        : "r"(a[0]), "r"(a[1]), "r"(a[2]), "r"(a[3]), "r"(b[0]), "r"(b[1]));
}

// ---------------------------------------------------------------------------
// Kernel 1: QKV projection via mma.sync (bf16 hi/lo x3). grid (B*C/64, 3),
// block 256. Writes Q (scaled by 1/sqrt32) and K/V pre-split hi/lo.
// smem: xhi[64][272B], xlo, whi[128][272B], wlo  => 104448 B
// ---------------------------------------------------------------------------
#define GX_HI 0
#define GX_LO 17408
#define GW_HI 34816
#define GW_LO 69632
#define GSMEM 104448

__global__ __launch_bounds__(256, 2) void qkv_mma(
    const float* __restrict__ x, const float* __restrict__ Wq,
    const float* __restrict__ Wk, const float* __restrict__ Wv)
{
    extern __shared__ char sm[];
    const u32 smb = smem_u32(sm);
    const int rt = blockIdx.x, mqkv = blockIdx.y, tid = threadIdx.x;
    const float* __restrict__ W = (mqkv == 0) ? Wq : ((mqkv == 1) ? Wk : Wv);

    // stage x tile 64x128 (split hi/lo)
    {
        const float4* xg = (const float4*)(x + (size_t)rt * 64 * 128);
        #pragma unroll
        for (int i = 0; i < 8; i++) {
            const int e = tid + i*256, row = e >> 5, c4 = e & 31;
            const float4 v = xg[e];
            u32 h0, h1, l0, l1;
            split2(v.x, v.y, h0, l0); split2(v.z, v.w, h1, l1);
            *(uint2*)(sm + GX_HI + row*272 + c4*8) = make_uint2(h0, h1);
            *(uint2*)(sm + GX_LO + row*272 + c4*8) = make_uint2(l0, l1);
        }
        const float4* wg = (const float4*)W;
        #pragma unroll
        for (int i = 0; i < 16; i++) {
            const int e = tid + i*256, row = e >> 5, c4 = e & 31;
            const float4 v = wg[e];
            u32 h0, h1, l0, l1;
            split2(v.x, v.y, h0, l0); split2(v.z, v.w, h1, l1);
            *(uint2*)(sm + GW_HI + row*272 + c4*8) = make_uint2(h0, h1);
            *(uint2*)(sm + GW_LO + row*272 + c4*8) = make_uint2(l0, l1);
        }
    }
    __syncthreads();

    const int wid = tid >> 5, lane = tid & 31;
    const int mi = wid >> 1, half = wid & 1;
    const int r = lane >> 2, qq = lane & 3;

    float c[8][4];
    #pragma unroll
    for (int i = 0; i < 8; i++)
        #pragma unroll
        for (int k = 0; k < 4; k++) c[i][k] = 0.f;

    const u32 fofs = (lane & 15)*272 + (lane >> 4)*16;
    const u32 aHi = smb + GX_HI + mi*16*272 + fofs;
    const u32 aLo = smb + GX_LO + mi*16*272 + fofs;
    const u32 bHi = smb + GW_HI + half*128 + fofs;
    const u32 bLo = smb + GW_LO + half*128 + fofs;

    #pragma unroll 1
    for (int kk = 0; kk < 8; kk++) {
        u32 ah[4], al[4];
        ldsm4(ah, aHi + kk*32);
        ldsm4(al, aLo + kk*32);
        u32 bh[16], bl[16];
        #pragma unroll
        for (int nt = 0; nt < 4; nt++) {
            ldsm4t(bh + nt*4, bHi + kk*16*272 + nt*32);
            ldsm4t(bl + nt*4, bLo + kk*16*272 + nt*32);
        }
        #pragma unroll
        for (int n8 = 0; n8 < 8; n8++) {
            mma16816(c[n8], ah, bh + n8*2);
            mma16816(c[n8], ah, bl + n8*2);
            mma16816(c[n8], al, bh + n8*2);
        }
    }

    const float scale = (mqkv == 0) ? 0.17677669529663687f : 1.0f;
    const int grow0 = rt*64 + mi*16 + r;
    #pragma unroll
    for (int n8 = 0; n8 < 8; n8++) {
        const int col = half*64 + n8*8 + 2*qq;
        #pragma unroll
        for (int rr = 0; rr < 2; rr++) {
            const int grow = grow0 + rr*8;
            u32 hi, lo;
            split2(c[n8][2*rr]*scale, c[n8][2*rr+1]*scale, hi, lo);
            if (mqkv == 0) {
                g_Qhi[(size_t)grow*64 + (col >> 1)] = hi;
                g_Qlo[(size_t)grow*64 + (col >> 1)] = lo;
            } else {
                const int bb = grow >> 11, key = grow & 2047;
                const int hh = col >> 5, d2 = (col & 31) >> 1;
                const size_t gi = ((size_t)(bb*4 + hh)*2048 + key)*16 + d2;
                if (mqkv == 1) { g_Khi[gi] = hi; g_Klo[gi] = lo; }
                else           { g_Vhi[gi] = hi; g_Vlo[gi] = lo; }
            }
        }
    }
}

// ---------------------------------------------------------------------------
// Kernel 2: attention. grid (C/128, B), block 256, 8 warps = (h, qsub).
// Each warp: 64 q-rows x 1 head. All staging is pure uint4 copies.
// ---------------------------------------------------------------------------
#define K_HI 0          // [4][64][80B]
#define K_LO 20480
#define V_HI 40960
#define V_LO 61440
#define ADJ  81920      // [128][68] f32 (premultiplied by log2e)
#define ASMEM 116736

__global__ __launch_bounds__(256, 1) void attn_mma(const float* __restrict__ adj)
{
    extern __shared__ char sm[];
    const u32 smb = smem_u32(sm);
    const int tid = threadIdx.x, wid = tid >> 5, lane = tid & 31;
    const int h = wid & 3, qsub = wid >> 2;
    const int r = lane >> 2, qq = lane & 3;
    const int q0 = blockIdx.x * QT, b = blockIdx.y;

    // ---- Q fragments (4 m16 tiles x 2 k16 slices), direct u32 loads ----
    u32 qhi[4][2][4], qlo[4][2][4];
    {
        const u32* Qh = g_Qhi + ((size_t)(b*Cz) + q0 + qsub*64)*64 + h*16;
        const u32* Ql = g_Qlo + ((size_t)(b*Cz) + q0 + qsub*64)*64 + h*16;
        #pragma unroll
        for (int m = 0; m < 4; m++)
            #pragma unroll
            for (int j = 0; j < 2; j++)
                #pragma unroll
                for (int p = 0; p < 4; p++) {
                    const int row = 16*m + r + (p & 1)*8;
                    const int ci  = 8*j + qq + (p >> 1)*4;
                    qhi[m][j][p] = Qh[(size_t)row*64 + ci];
                    qlo[m][j][p] = Ql[(size_t)row*64 + ci];
                }
    }

    float o[4][4][4];
    #pragma unroll
    for (int m = 0; m < 4; m++)
        #pragma unroll
        for (int dt = 0; dt < 4; dt++)
            #pragma unroll
            for (int k = 0; k < 4; k++) o[m][dt][k] = 0.f;
    float rs[8] = {0.f,0.f,0.f,0.f,0.f,0.f,0.f,0.f};

    const u32 kofs = (lane & 7)*80 + (lane >> 3)*16;
    const u32 vofs = (lane & 15)*80 + (lane >> 4)*16;
    const u32 KhiB = smb + K_HI + h*5120 + kofs;
    const u32 KloB = smb + K_LO + h*5120 + kofs;
    const u32 VhiB = smb + V_HI + h*5120 + vofs;
    const u32 VloB = smb + V_LO + h*5120 + vofs;
    const float* adjs  = (const float*)(sm + ADJ) + (qsub*64 + r)*68 + 2*qq;
    const float* adj_g = adj + ((size_t)b*Cz + q0)*Cz;

    const u32* KhiG = g_Khi + (size_t)b*4*2048*16;
    const u32* KloG = g_Klo + (size_t)b*4*2048*16;
    const u32* VhiG = g_Vhi + (size_t)b*4*2048*16;
    const u32* VloG = g_Vlo + (size_t)b*4*2048*16;

    #pragma unroll 1
    for (int it = 0; it < NIT; it++) {
        const int k0 = it * KT;
        __syncthreads();
        // ---- stage K/V (pure copies) ----
        #pragma unroll
        for (int i = 0; i < 4; i++) {
            const int e = tid + i*256;
            const int hh = e >> 8, key = (e >> 2) & 63, part = e & 3;
            const size_t gi = ((size_t)hh*2048 + k0 + key)*16 + part*4;
            const u32 so = (u32)(hh*5120 + key*80 + part*16);
            *(uint4*)(sm + K_HI + so) = *(const uint4*)(KhiG + gi);
            *(uint4*)(sm + K_LO + so) = *(const uint4*)(KloG + gi);
            *(uint4*)(sm + V_HI + so) = *(const uint4*)(VhiG + gi);
            *(uint4*)(sm + V_LO + so) = *(const uint4*)(VloG + gi);
        }
        // ---- stage adj premultiplied by log2e ----
        #pragma unroll
        for (int i = 0; i < 8; i++) {
            const int e = tid + i*256, row = e >> 4, c4 = e & 15;
            float4 a = *(const float4*)(adj_g + (size_t)row*Cz + k0 + c4*4);
            a.x *= LOG2E; a.y *= LOG2E; a.z *= LOG2E; a.w *= LOG2E;
            *(float4*)(sm + ADJ + (row*68 + c4*4)*4) = a;
        }
        __syncthreads();

        #pragma unroll
        for (int j = 0; j < 4; j++) {
            u32 bh0[4], bl0[4], bh1[4], bl1[4];
            ldsm4(bh0, KhiB + (2*j)*640);
            ldsm4(bl0, KloB + (2*j)*640);
            ldsm4(bh1, KhiB + (2*j+1)*640);
            ldsm4(bl1, KloB + (2*j+1)*640);
            u32 vh[8], vl[8];
            ldsm4t(vh,     VhiB + j*1280);
            ldsm4t(vh + 4, VhiB + j*1280 + 32);
            ldsm4t(vl,     VloB + j*1280);
            ldsm4t(vl + 4, VloB + j*1280 + 32);

            #pragma unroll
            for (int m = 0; m < 4; m++) {
                u32 pa[4], pl[4];
                #pragma unroll
                for (int ii = 0; ii < 2; ii++) {
                    const u32* bh = ii ? bh1 : bh0;
                    const u32* bl = ii ? bl1 : bl0;
                    float S[4] = {0.f, 0.f, 0.f, 0.f};
                    mma16816(S, qhi[m][0], bh);
                    mma16816(S, qhi[m][1], bh + 2);
                    mma16816(S, qhi[m][0], bl);
                    mma16816(S, qhi[m][1], bl + 2);
                    mma16816(S, qlo[m][0], bh);
                    mma16816(S, qlo[m][1], bh + 2);

                    const float* ar = adjs + (16*m)*68 + 8*(2*j + ii);
                    const float2 a01 = *(const float2*)ar;
                    const float2 a23 = *(const float2*)(ar + 8*68);
                    float t0 = S[0]*a01.x; t0 = fmaxf(t0, 0.2f*t0);
                    float t1 = S[1]*a01.y; t1 = fmaxf(t1, 0.2f*t1);
                    float t2 = S[2]*a23.x; t2 = fmaxf(t2, 0.2f*t2);
                    float t3 = S[3]*a23.y; t3 = fmaxf(t3, 0.2f*t3);
                    const float p0 = ex2f(t0), p1 = ex2f(t1);
                    const float p2 = ex2f(t2), p3 = ex2f(t3);
                    rs[2*m]   += p0 + p1;
                    rs[2*m+1] += p2 + p3;
                    split2(p0, p1, pa[2*ii],   pl[2*ii]);
                    split2(p2, p3, pa[2*ii+1], pl[2*ii+1]);
                }
                #pragma unroll
                for (int dt = 0; dt < 4; dt++) {
                    mma16816(o[m][dt], pa, vh + 2*dt);
                    mma16816(o[m][dt], pa, vl + 2*dt);
                    mma16816(o[m][dt], pl, vh + 2*dt);
                }
            }
        }
    }

    // ---- rowsum reduce across quad, normalize, split hi/lo, store ----
    #pragma unroll
    for (int k = 0; k < 8; k++) {
        rs[k] += __shfl_xor_sync(0xFFFFFFFFu, rs[k], 1);
        rs[k] += __shfl_xor_sync(0xFFFFFFFFu, rs[k], 2);
    }
    #pragma unroll
    for (int m = 0; m < 4; m++) {
        const float inv0 = 1.0f / rs[2*m], inv1 = 1.0f / rs[2*m+1];
        const int row0 = q0 + qsub*64 + 16*m + r;
        #pragma unroll
        for (int dt = 0; dt < 4; dt++) {
            u32 hi, lo;
            split2(o[m][dt][0]*inv0, o[m][dt][1]*inv0, hi, lo);
            size_t gi = ((size_t)(b*Cz) + row0)*64 + h*16 + dt*4 + qq;
            g_Ahi[gi] = hi; g_Alo[gi] = lo;
            split2(o[m][dt][2]*inv1, o[m][dt][3]*inv1, hi, lo);
            gi = ((size_t)(b*Cz) + row0 + 8)*64 + h*16 + dt*4 + qq;
            g_Ahi[gi] = hi; g_Alo[gi] = lo;
        }
    }
}

// ---------------------------------------------------------------------------
// Kernel 3: output projection via mma.sync, A pre-split. grid (B*C/64), 256.
// ---------------------------------------------------------------------------
__global__ __launch_bounds__(256, 2) void out_mma(
    const float* __restrict__ Wo, const float* __restrict__ bo,
    float* __restrict__ out)
{
    extern __shared__ char sm[];
    const u32 smb = smem_u32(sm);
    const int rt = blockIdx.x, tid = threadIdx.x;

    // stage A (pure copies) and Wo (split hi/lo)
    {
        const uint4* ah = (const uint4*)(g_Ahi + (size_t)rt*64*64);
        const uint4* al = (const uint4*)(g_Alo + (size_t)rt*64*64);
        #pragma unroll
        for (int i = 0; i < 4; i++) {
            const int e = tid + i*256, row = e >> 4, c4 = e & 15;
            *(uint4*)(sm + GX_HI + row*272 + c4*16) = ah[e];
            *(uint4*)(sm + GX_LO + row*272 + c4*16) = al[e];
        }
        const float4* wg = (const float4*)Wo;
        #pragma unroll
        for (int i = 0; i < 16; i++) {
            const int e = tid + i*256, row = e >> 5, c4 = e & 31;
            const float4 v = wg[e];
            u32 h0, h1, l0, l1;
            split2(v.x, v.y, h0, l0); split2(v.z, v.w, h1, l1);
            *(uint2*)(sm + GW_HI + row*272 + c4*8) = make_uint2(h0, h1);
            *(uint2*)(sm + GW_LO + row*272 + c4*8) = make_uint2(l0, l1);
        }
    }
    __syncthreads();

    const int wid = tid >> 5, lane = tid & 31;
    const int mi = wid >> 1, half = wid & 1;
    const int r = lane >> 2, qq = lane & 3;

    float c[8][4];
    #pragma unroll
    for (int i = 0; i < 8; i++)
        #pragma unroll
        for (int k = 0; k < 4; k++) c[i][k] = 0.f;

    const u32 fofs = (lane & 15)*272 + (lane >> 4)*16;
    const u32 aHi = smb + GX_HI + mi*16*272 + fofs;
    const u32 aLo = smb + GX_LO + mi*16*272 + fofs;
    const u32 bHi = smb + GW_HI + half*128 + fofs;
    const u32 bLo = smb + GW_LO + half*128 + fofs;

    #pragma unroll 1
    for (int kk = 0; kk < 8; kk++) {
        u32 ah[4], al[4];
        ldsm4(ah, aHi + kk*32);
        ldsm4(al, aLo + kk*32);
        u32 bh[16], bl[16];
        #pragma unroll
        for (int nt = 0; nt < 4; nt++) {
            ldsm4t(bh + nt*4, bHi + kk*16*272 + nt*32);
            ldsm4t(bl + nt*4, bLo + kk*16*272 + nt*32);
        }
        #pragma unroll
        for (int n8 = 0; n8 < 8; n8++) {
            mma16816(c[n8], ah, bh + n8*2);
            mma16816(c[n8], ah, bl + n8*2);
            mma16816(c[n8], al, bh + n8*2);
        }
    }

    const int grow0 = rt*64 + mi*16 + r;
    #pragma unroll
    for (int n8 = 0; n8 < 8; n8++) {
        const int col = half*64 + n8*8 + 2*qq;
        const float2 bv = *(const float2*)(bo + col);
        #pragma unroll
        for (int rr = 0; rr < 2; rr++) {
            const int grow = grow0 + rr*8;
            float2 v = make_float2(c[n8][2*rr] + bv.x, c[n8][2*rr+1] + bv.y);
            *(float2*)(out + (size_t)grow*128 + col) = v;
        }
    }
}

// ---------------------------------------------------------------------------
extern "C" void kernel_launch(void* const* d_in, const int* in_sizes, int n_in,
                              void* d_out, int out_size)
{
    const float* x   = (const float*)d_in[0];
    const float* adj = (const float*)d_in[1];
    const float* Wq  = (const float*)d_in[2];
    const float* Wk  = (const float*)d_in[3];
    const float* Wv  = (const float*)d_in[4];
    const float* Wo  = (const float*)d_in[5];
    const float* bo  = (const float*)d_in[6];
    float* out = (float*)d_out;

    cudaFuncSetAttribute(qkv_mma,  cudaFuncAttributeMaxDynamicSharedMemorySize, GSMEM);
    cudaFuncSetAttribute(attn_mma, cudaFuncAttributeMaxDynamicSharedMemorySize, ASMEM);
    cudaFuncSetAttribute(out_mma,  cudaFuncAttributeMaxDynamicSharedMemorySize, GSMEM);

    qkv_mma<<<dim3(Bz*Cz/64, 3), 256, GSMEM>>>(x, Wq, Wk, Wv);
    attn_mma<<<dim3(Cz/QT, Bz), 256, ASMEM>>>(adj);
    out_mma<<<Bz*Cz/64, 256, GSMEM>>>(Wo, bo, out);
}

// round 12
// speedup vs baseline: 3.3681x; 1.1820x over previous
#include <cuda_runtime.h>
#include <cuda_bf16.h>
#include <cuda_fp16.h>

typedef unsigned int u32;
typedef unsigned long long u64;

#define Bz 8
#define Cz 2048
#define HD 128
#define QT 128
#define KT 64
#define NIT (Cz/KT)
#define LOG2E 1.4426950408889634f

// hi/lo scratch, packed as 2-elem words (even col in low half)
__device__ u32 g_Qhi[Bz*Cz*64], g_Qlo[Bz*Cz*64];        // bf16x2 [b*C + c][64]
__device__ u32 g_Khi[Bz*4*Cz*16], g_Klo[Bz*4*Cz*16];    // bf16x2 [b*4+h][key][16]
__device__ u32 g_Vhi[Bz*4*Cz*16], g_Vlo[Bz*4*Cz*16];    // fp16x2 [b*4+h][key][16]
__device__ u32 g_Ahi[Bz*Cz*64], g_Alo[Bz*Cz*64];        // bf16x2 attention output

// ---------------- helpers ---------------------------------------------------
__device__ __forceinline__ u32 smem_u32(const void* p) {
    u32 a;
    asm("{ .reg .u64 t; cvta.to.shared.u64 t, %1; cvt.u32.u64 %0, t; }" : "=r"(a) : "l"(p));
    return a;
}
__device__ __forceinline__ u32 cvt2(float hi, float lo) {       // bf16x2
    u32 r; asm("cvt.rn.bf16x2.f32 %0, %1, %2;" : "=r"(r) : "f"(hi), "f"(lo)); return r;
}
__device__ __forceinline__ u32 cvt2h(float hi, float lo) {      // fp16x2
    u32 r; asm("cvt.rn.f16x2.f32 %0, %1, %2;" : "=r"(r) : "f"(hi), "f"(lo)); return r;
}
__device__ __forceinline__ float2 ub2(u32 v) {
    __nv_bfloat162 t = *reinterpret_cast<__nv_bfloat162*>(&v);
    return __bfloat1622float2(t);
}
__device__ __forceinline__ float2 uh2(u32 v) {
    __half2 t = *reinterpret_cast<__half2*>(&v);
    return __half22float2(t);
}
__device__ __forceinline__ void split2(float x0, float x1, u32& hi, u32& lo) {
    hi = cvt2(x1, x0);
    float2 f = ub2(hi);
    lo = cvt2(x1 - f.y, x0 - f.x);
}
__device__ __forceinline__ void split2h(float x0, float x1, u32& hi, u32& lo) {
    hi = cvt2h(x1, x0);
    float2 f = uh2(hi);
    lo = cvt2h(x1 - f.y, x0 - f.x);
}
__device__ __forceinline__ float ex2f(float x) {
    float y; asm("ex2.approx.f32 %0, %1;" : "=f"(y) : "f"(x)); return y;
}
__device__ __forceinline__ void ldsm4(u32* r, u32 addr) {
    asm volatile("ldmatrix.sync.aligned.m8n8.x4.shared.b16 {%0,%1,%2,%3}, [%4];"
        : "=r"(r[0]), "=r"(r[1]), "=r"(r[2]), "=r"(r[3]) : "r"(addr));
}
__device__ __forceinline__ void ldsm4t(u32* r, u32 addr) {
    asm volatile("ldmatrix.sync.aligned.m8n8.x4.trans.shared.b16 {%0,%1,%2,%3}, [%4];"
        : "=r"(r[0]), "=r"(r[1]), "=r"(r[2]), "=r"(r[3]) : "r"(addr));
}
__device__ __forceinline__ void mma16816(float* c, const u32* a, const u32* b) {
    asm volatile("mma.sync.aligned.m16n8k16.row.col.f32.bf16.bf16.f32 "
        "{%0,%1,%2,%3}, {%4,%5,%6,%7}, {%8,%9}, {%0,%1,%2,%3};"
        : "+f"(c[0]), "+f"(c[1]), "+f"(c[2]), "+f"(c[3])
        : "r"(a[0]), "r"(a[1]), "r"(a[2]), "r"(a[3]), "r"(b[0]), "r"(b[1]));
}
__device__ __forceinline__ void mma16816h(float* c, const u32* a, const u32* b) {
    asm volatile("mma.sync.aligned.m16n8k16.row.col.f32.f16.f16.f32 "
        "{%0,%1,%2,%3}, {%4,%5,%6,%7}, {%8,%9}, {%0,%1,%2,%3};"
        : "+f"(c[0]), "+f"(c[1]), "+f"(c[2]), "+f"(c[3])
        : "r"(a[0]), "r"(a[1]), "r"(a[2]), "r"(a[3]), "r"(b[0]), "r"(b[1]));
}

// ---------------------------------------------------------------------------
// Kernel 1: QKV projection via mma.sync (bf16 hi/lo x3). grid (B*C/64, 3),
// block 256. Q/K pre-split bf16 hi/lo; V pre-split fp16 hi/lo.
// ---------------------------------------------------------------------------
#define GX_HI 0
#define GX_LO 17408
#define GW_HI 34816
#define GW_LO 69632
#define GSMEM 104448

__global__ __launch_bounds__(256, 2) void qkv_mma(
    const float* __restrict__ x, const float* __restrict__ Wq,
    const float* __restrict__ Wk, const float* __restrict__ Wv)
{
    extern __shared__ char sm[];
    const u32 smb = smem_u32(sm);
    const int rt = blockIdx.x, mqkv = blockIdx.y, tid = threadIdx.x;
    const float* __restrict__ W = (mqkv == 0) ? Wq : ((mqkv == 1) ? Wk : Wv);

    {
        const float4* xg = (const float4*)(x + (size_t)rt * 64 * 128);
        #pragma unroll
        for (int i = 0; i < 8; i++) {
            const int e = tid + i*256, row = e >> 5, c4 = e & 31;
            const float4 v = xg[e];
            u32 h0, h1, l0, l1;
            split2(v.x, v.y, h0, l0); split2(v.z, v.w, h1, l1);
            *(uint2*)(sm + GX_HI + row*272 + c4*8) = make_uint2(h0, h1);
            *(uint2*)(sm + GX_LO + row*272 + c4*8) = make_uint2(l0, l1);
        }
        const float4* wg = (const float4*)W;
        #pragma unroll
        for (int i = 0; i < 16; i++) {
            const int e = tid + i*256, row = e >> 5, c4 = e & 31;
            const float4 v = wg[e];
            u32 h0, h1, l0, l1;
            split2(v.x, v.y, h0, l0); split2(v.z, v.w, h1, l1);
            *(uint2*)(sm + GW_HI + row*272 + c4*8) = make_uint2(h0, h1);
            *(uint2*)(sm + GW_LO + row*272 + c4*8) = make_uint2(l0, l1);
        }
    }
    __syncthreads();

    const int wid = tid >> 5, lane = tid & 31;
    const int mi = wid >> 1, half = wid & 1;
    const int r = lane >> 2, qq = lane & 3;

    float c[8][4];
    #pragma unroll
    for (int i = 0; i < 8; i++)
        #pragma unroll
        for (int k = 0; k < 4; k++) c[i][k] = 0.f;

    const u32 fofs = (lane & 15)*272 + (lane >> 4)*16;
    const u32 aHi = smb + GX_HI + mi*16*272 + fofs;
    const u32 aLo = smb + GX_LO + mi*16*272 + fofs;
    const u32 bHi = smb + GW_HI + half*128 + fofs;
    const u32 bLo = smb + GW_LO + half*128 + fofs;

    #pragma unroll 1
    for (int kk = 0; kk < 8; kk++) {
        u32 ah[4], al[4];
        ldsm4(ah, aHi + kk*32);
        ldsm4(al, aLo + kk*32);
        u32 bh[16], bl[16];
        #pragma unroll
        for (int nt = 0; nt < 4; nt++) {
            ldsm4t(bh + nt*4, bHi + kk*16*272 + nt*32);
            ldsm4t(bl + nt*4, bLo + kk*16*272 + nt*32);
        }
        #pragma unroll
        for (int n8 = 0; n8 < 8; n8++) {
            mma16816(c[n8], ah, bh + n8*2);
            mma16816(c[n8], ah, bl + n8*2);
            mma16816(c[n8], al, bh + n8*2);
        }
    }

    const float scale = (mqkv == 0) ? 0.17677669529663687f : 1.0f;
    const int grow0 = rt*64 + mi*16 + r;
    #pragma unroll
    for (int n8 = 0; n8 < 8; n8++) {
        const int col = half*64 + n8*8 + 2*qq;
        #pragma unroll
        for (int rr = 0; rr < 2; rr++) {
            const int grow = grow0 + rr*8;
            u32 hi, lo;
            if (mqkv == 2) split2h(c[n8][2*rr], c[n8][2*rr+1], hi, lo);
            else           split2(c[n8][2*rr]*scale, c[n8][2*rr+1]*scale, hi, lo);
            if (mqkv == 0) {
                g_Qhi[(size_t)grow*64 + (col >> 1)] = hi;
                g_Qlo[(size_t)grow*64 + (col >> 1)] = lo;
            } else {
                const int bb = grow >> 11, key = grow & 2047;
                const int hh = col >> 5, d2 = (col & 31) >> 1;
                const size_t gi = ((size_t)(bb*4 + hh)*2048 + key)*16 + d2;
                if (mqkv == 1) { g_Khi[gi] = hi; g_Klo[gi] = lo; }
                else           { g_Vhi[gi] = hi; g_Vlo[gi] = lo; }
            }
        }
    }
}

// ---------------------------------------------------------------------------
// Kernel 2: attention. grid (C/128, B), block 512, 16 warps = (h, qsub).
// Each warp: 32 q-rows x 1 head. QK bf16 hi/lo x3; PV fp16 (P single, V hi/lo).
// ---------------------------------------------------------------------------
#define K_HI 0          // [4][64][80B]
#define K_LO 20480
#define V_HI 40960
#define V_LO 61440
#define ADJ  81920      // [128][68] f32 (premultiplied by log2e)
#define ASMEM 116736

__global__ __launch_bounds__(512, 1) void attn_mma(const float* __restrict__ adj)
{
    extern __shared__ char sm[];
    const u32 smb = smem_u32(sm);
    const int tid = threadIdx.x, wid = tid >> 5, lane = tid & 31;
    const int h = wid & 3, qsub = wid >> 2;
    const int r = lane >> 2, qq = lane & 3;
    const int q0 = blockIdx.x * QT, b = blockIdx.y;

    // ---- Q fragments (2 m16 tiles x 2 k16 slices) ----
    u32 qhi[2][2][4], qlo[2][2][4];
    {
        const u32* Qh = g_Qhi + ((size_t)(b*Cz) + q0 + qsub*32)*64 + h*16;
        const u32* Ql = g_Qlo + ((size_t)(b*Cz) + q0 + qsub*32)*64 + h*16;
        #pragma unroll
        for (int m = 0; m < 2; m++)
            #pragma unroll
            for (int j = 0; j < 2; j++)
                #pragma unroll
                for (int p = 0; p < 4; p++) {
                    const int row = 16*m + r + (p & 1)*8;
                    const int ci  = 8*j + qq + (p >> 1)*4;
                    qhi[m][j][p] = Qh[(size_t)row*64 + ci];
                    qlo[m][j][p] = Ql[(size_t)row*64 + ci];
                }
    }

    float o[2][4][4];
    #pragma unroll
    for (int m = 0; m < 2; m++)
        #pragma unroll
        for (int dt = 0; dt < 4; dt++)
            #pragma unroll
            for (int k = 0; k < 4; k++) o[m][dt][k] = 0.f;
    float rs[4] = {0.f, 0.f, 0.f, 0.f};

    const u32 kofs = (lane & 7)*80 + (lane >> 3)*16;
    const u32 vofs = (lane & 15)*80 + (lane >> 4)*16;
    const u32 KhiB = smb + K_HI + h*5120 + kofs;
    const u32 KloB = smb + K_LO + h*5120 + kofs;
    const u32 VhiB = smb + V_HI + h*5120 + vofs;
    const u32 VloB = smb + V_LO + h*5120 + vofs;
    const float* adjs  = (const float*)(sm + ADJ) + (qsub*32 + r)*68 + 2*qq;
    const float* adj_g = adj + ((size_t)b*Cz + q0)*Cz;

    const u32* KhiG = g_Khi + (size_t)b*4*2048*16;
    const u32* KloG = g_Klo + (size_t)b*4*2048*16;
    const u32* VhiG = g_Vhi + (size_t)b*4*2048*16;
    const u32* VloG = g_Vlo + (size_t)b*4*2048*16;

    #pragma unroll 1
    for (int it = 0; it < NIT; it++) {
        const int k0 = it * KT;
        __syncthreads();
        // ---- stage K/V (pure uint4 copies; 1024 uint4 per array) ----
        #pragma unroll
        for (int i = 0; i < 2; i++) {
            const int e = tid + i*512;
            const int hh = e >> 8, key = (e >> 2) & 63, part = e & 3;
            const size_t gi = ((size_t)hh*2048 + k0 + key)*16 + part*4;
            const u32 so = (u32)(hh*5120 + key*80 + part*16);
            *(uint4*)(sm + K_HI + so) = *(const uint4*)(KhiG + gi);
            *(uint4*)(sm + K_LO + so) = *(const uint4*)(KloG + gi);
            *(uint4*)(sm + V_HI + so) = *(const uint4*)(VhiG + gi);
            *(uint4*)(sm + V_LO + so) = *(const uint4*)(VloG + gi);
        }
        // ---- stage adj premultiplied by log2e (2048 float4) ----
        #pragma unroll
        for (int i = 0; i < 4; i++) {
            const int e = tid + i*512, row = e >> 4, c4 = e & 15;
            float4 a = *(const float4*)(adj_g + (size_t)row*Cz + k0 + c4*4);
            a.x *= LOG2E; a.y *= LOG2E; a.z *= LOG2E; a.w *= LOG2E;
            *(float4*)(sm + ADJ + (row*68 + c4*4)*4) = a;
        }
        __syncthreads();

        #pragma unroll
        for (int j = 0; j < 4; j++) {
            u32 bh0[4], bl0[4], bh1[4], bl1[4];
            ldsm4(bh0, KhiB + (2*j)*640);
            ldsm4(bl0, KloB + (2*j)*640);
            ldsm4(bh1, KhiB + (2*j+1)*640);
            ldsm4(bl1, KloB + (2*j+1)*640);
            u32 vh[8], vl[8];
            ldsm4t(vh,     VhiB + j*1280);
            ldsm4t(vh + 4, VhiB + j*1280 + 32);
            ldsm4t(vl,     VloB + j*1280);
            ldsm4t(vl + 4, VloB + j*1280 + 32);

            #pragma unroll
            for (int m = 0; m < 2; m++) {
                u32 pa[4];
                #pragma unroll
                for (int ii = 0; ii < 2; ii++) {
                    const u32* bh = ii ? bh1 : bh0;
                    const u32* bl = ii ? bl1 : bl0;
                    float S[4] = {0.f, 0.f, 0.f, 0.f};
                    mma16816(S, qhi[m][0], bh);
                    mma16816(S, qhi[m][1], bh + 2);
                    mma16816(S, qhi[m][0], bl);
                    mma16816(S, qhi[m][1], bl + 2);
                    mma16816(S, qlo[m][0], bh);
                    mma16816(S, qlo[m][1], bh + 2);

                    const float* ar = adjs + (16*m)*68 + 8*(2*j + ii);
                    const float2 a01 = *(const float2*)ar;
                    const float2 a23 = *(const float2*)(ar + 8*68);
                    float t0 = S[0]*a01.x; t0 = fmaxf(t0, 0.2f*t0);
                    float t1 = S[1]*a01.y; t1 = fmaxf(t1, 0.2f*t1);
                    float t2 = S[2]*a23.x; t2 = fmaxf(t2, 0.2f*t2);
                    float t3 = S[3]*a23.y; t3 = fmaxf(t3, 0.2f*t3);
                    const float p0 = ex2f(t0), p1 = ex2f(t1);
                    const float p2 = ex2f(t2), p3 = ex2f(t3);
                    rs[2*m]   += p0 + p1;
                    rs[2*m+1] += p2 + p3;
                    pa[2*ii]   = cvt2h(p1, p0);
                    pa[2*ii+1] = cvt2h(p3, p2);
                }
                #pragma unroll
                for (int dt = 0; dt < 4; dt++) {
                    mma16816h(o[m][dt], pa, vh + 2*dt);
                    mma16816h(o[m][dt], pa, vl + 2*dt);
                }
            }
        }
    }

    // ---- rowsum reduce across quad, normalize, split hi/lo, store ----
    #pragma unroll
    for (int k = 0; k < 4; k++) {
        rs[k] += __shfl_xor_sync(0xFFFFFFFFu, rs[k], 1);
        rs[k] += __shfl_xor_sync(0xFFFFFFFFu, rs[k], 2);
    }
    #pragma unroll
    for (int m = 0; m < 2; m++) {
        const float inv0 = 1.0f / rs[2*m], inv1 = 1.0f / rs[2*m+1];
        const int row0 = q0 + qsub*32 + 16*m + r;
        #pragma unroll
        for (int dt = 0; dt < 4; dt++) {
            u32 hi, lo;
            split2(o[m][dt][0]*inv0, o[m][dt][1]*inv0, hi, lo);
            size_t gi = ((size_t)(b*Cz) + row0)*64 + h*16 + dt*4 + qq;
            g_Ahi[gi] = hi; g_Alo[gi] = lo;
            split2(o[m][dt][2]*inv1, o[m][dt][3]*inv1, hi, lo);
            gi = ((size_t)(b*Cz) + row0 + 8)*64 + h*16 + dt*4 + qq;
            g_Ahi[gi] = hi; g_Alo[gi] = lo;
        }
    }
}

// ---------------------------------------------------------------------------
// Kernel 3: output projection via mma.sync, A pre-split. grid (B*C/64), 256.
// ---------------------------------------------------------------------------
__global__ __launch_bounds__(256, 2) void out_mma(
    const float* __restrict__ Wo, const float* __restrict__ bo,
    float* __restrict__ out)
{
    extern __shared__ char sm[];
    const u32 smb = smem_u32(sm);
    const int rt = blockIdx.x, tid = threadIdx.x;

    {
        const uint4* ah = (const uint4*)(g_Ahi + (size_t)rt*64*64);
        const uint4* al = (const uint4*)(g_Alo + (size_t)rt*64*64);
        #pragma unroll
        for (int i = 0; i < 4; i++) {
            const int e = tid + i*256, row = e >> 4, c4 = e & 15;
            *(uint4*)(sm + GX_HI + row*272 + c4*16) = ah[e];
            *(uint4*)(sm + GX_LO + row*272 + c4*16) = al[e];
        }
        const float4* wg = (const float4*)Wo;
        #pragma unroll
        for (int i = 0; i < 16; i++) {
            const int e = tid + i*256, row = e >> 5, c4 = e & 31;
            const float4 v = wg[e];
            u32 h0, h1, l0, l1;
            split2(v.x, v.y, h0, l0); split2(v.z, v.w, h1, l1);
            *(uint2*)(sm + GW_HI + row*272 + c4*8) = make_uint2(h0, h1);
            *(uint2*)(sm + GW_LO + row*272 + c4*8) = make_uint2(l0, l1);
        }
    }
    __syncthreads();

    const int wid = tid >> 5, lane = tid & 31;
    const int mi = wid >> 1, half = wid & 1;
    const int r = lane >> 2, qq = lane & 3;

    float c[8][4];
    #pragma unroll
    for (int i = 0; i < 8; i++)
        #pragma unroll
        for (int k = 0; k < 4; k++) c[i][k] = 0.f;

    const u32 fofs = (lane & 15)*272 + (lane >> 4)*16;
    const u32 aHi = smb + GX_HI + mi*16*272 + fofs;
    const u32 aLo = smb + GX_LO + mi*16*272 + fofs;
    const u32 bHi = smb + GW_HI + half*128 + fofs;
    const u32 bLo = smb + GW_LO + half*128 + fofs;

    #pragma unroll 1
    for (int kk = 0; kk < 8; kk++) {
        u32 ah[4], al[4];
        ldsm4(ah, aHi + kk*32);
        ldsm4(al, aLo + kk*32);
        u32 bh[16], bl[16];
        #pragma unroll
        for (int nt = 0; nt < 4; nt++) {
            ldsm4t(bh + nt*4, bHi + kk*16*272 + nt*32);
            ldsm4t(bl + nt*4, bLo + kk*16*272 + nt*32);
        }
        #pragma unroll
        for (int n8 = 0; n8 < 8; n8++) {
            mma16816(c[n8], ah, bh + n8*2);
            mma16816(c[n8], ah, bl + n8*2);
            mma16816(c[n8], al, bh + n8*2);
        }
    }

    const int grow0 = rt*64 + mi*16 + r;
    #pragma unroll
    for (int n8 = 0; n8 < 8; n8++) {
        const int col = half*64 + n8*8 + 2*qq;
        const float2 bv = *(const float2*)(bo + col);
        #pragma unroll
        for (int rr = 0; rr < 2; rr++) {
            const int grow = grow0 + rr*8;
            float2 v = make_float2(c[n8][2*rr] + bv.x, c[n8][2*rr+1] + bv.y);
            *(float2*)(out + (size_t)grow*128 + col) = v;
        }
    }
}

// ---------------------------------------------------------------------------
extern "C" void kernel_launch(void* const* d_in, const int* in_sizes, int n_in,
                              void* d_out, int out_size)
{
    const float* x   = (const float*)d_in[0];
    const float* adj = (const float*)d_in[1];
    const float* Wq  = (const float*)d_in[2];
    const float* Wk  = (const float*)d_in[3];
    const float* Wv  = (const float*)d_in[4];
    const float* Wo  = (const float*)d_in[5];
    const float* bo  = (const float*)d_in[6];
    float* out = (float*)d_out;

    cudaFuncSetAttribute(qkv_mma,  cudaFuncAttributeMaxDynamicSharedMemorySize, GSMEM);
    cudaFuncSetAttribute(attn_mma, cudaFuncAttributeMaxDynamicSharedMemorySize, ASMEM);
    cudaFuncSetAttribute(out_mma,  cudaFuncAttributeMaxDynamicSharedMemorySize, GSMEM);

    qkv_mma<<<dim3(Bz*Cz/64, 3), 256, GSMEM>>>(x, Wq, Wk, Wv);
    attn_mma<<<dim3(Cz/QT, Bz), 512, ASMEM>>>(adj);
    out_mma<<<Bz*Cz/64, 256, GSMEM>>>(Wo, bo, out);
}